// round 5
// baseline (speedup 1.0000x reference)
#include <cuda_runtime.h>
#include <math.h>

// ---------------------------------------------------------------------------
// Problem constants
// ---------------------------------------------------------------------------
#define BB    2
#define NN    1024
#define DIMM  512
#define HEADS 8
#define DH    64
#define INNER 512          // HEADS*DH
#define FF    2048         // DIM*4
#define ROWS  (BB*NN)      // 2048
#define EPS   1e-6f
#define ATT_SCALE 0.125f   // DH^-0.5

// plane stride for planar q/k/v and attn buffers: B*H*N*DH = 2*8*1024*64
#define PLANE (1u<<20)

// ---------------------------------------------------------------------------
// Scratch (device globals; no allocation allowed)
// ---------------------------------------------------------------------------
__device__ float g_x  [ROWS*DIMM*2];      // running residual (complex interleaved)
__device__ float g_h  [ROWS*DIMM*2];      // rmsnorm output
__device__ float g_q  [ROWS*INNER*2];     // q = h @ Wq
__device__ float g_kv [ROWS*2*INNER*2];   // kv = h @ Wkv
__device__ float g_qp [2*PLANE];          // planar [comp][b][h][n][dh], rope applied
__device__ float g_kp [2*PLANE];
__device__ float g_vp [2*PLANE];
__device__ float g_attn[4*PLANE];         // 4 variants (rr, ri, ir, ii)
__device__ float g_o  [ROWS*INNER*2];     // combined complex attention output
__device__ float g_ff [ROWS*FF*2];        // feed-forward hidden

// ---------------------------------------------------------------------------
// copy kernel (x -> g_x), float4
// ---------------------------------------------------------------------------
__global__ void copy_kernel(const float4* __restrict__ src, float4* __restrict__ dst, int n4)
{
    int i = blockIdx.x * blockDim.x + threadIdx.x;
    if (i < n4) dst[i] = src[i];
}

// ---------------------------------------------------------------------------
// RMSNorm over complex last dim (DIM), times complex gamma
// one block per row, 256 threads
// ---------------------------------------------------------------------------
__global__ void rmsnorm_kernel(const float* __restrict__ x,
                               const float* __restrict__ gamma,
                               float* __restrict__ out)
{
    int row = blockIdx.x;
    const float* xr = x + (size_t)row * (DIMM*2);
    float* orow = out + (size_t)row * (DIMM*2);
    __shared__ float red[256];
    int tid = threadIdx.x;
    float s = 0.f;
    for (int e = tid; e < DIMM; e += 256) {
        float a = xr[2*e], b = xr[2*e+1];
        s += a*a + b*b;
    }
    red[tid] = s;
    __syncthreads();
    for (int off = 128; off > 0; off >>= 1) {
        if (tid < off) red[tid] += red[tid + off];
        __syncthreads();
    }
    float ms = red[0] * (1.f / DIMM);
    float sc = 1.f / sqrtf(ms + EPS);
    for (int e = tid; e < DIMM; e += 256) {
        float a = xr[2*e] * sc, b = xr[2*e+1] * sc;
        float gr = gamma[2*e], gi = gamma[2*e+1];
        orow[2*e]   = a*gr - b*gi;
        orow[2*e+1] = a*gi + b*gr;
    }
}

// ---------------------------------------------------------------------------
// Complex GEMM as real GEMM: C(M x 2Nc) = A(M x 2Kc) * Breal(2Kc x 2Nc)
// where Breal[2k+p][2n+q] = {(0,0):Wr, (0,1):Wi, (1,0):-Wi, (1,1):Wr}.
// Tiles 128x64x16, 256 threads, 8x4 register tile, double-buffered smem.
// W staged as one float2 per complex weight (coalesced), expanded 2x2 in smem.
// Optional bias (real view, length 2Nc) and residual (same layout as C).
// ---------------------------------------------------------------------------
__global__ void __launch_bounds__(256)
cgemm_kernel(const float* __restrict__ A,
             const float* __restrict__ W,
             const float* __restrict__ bias,
             const float* __restrict__ resid,
             float* __restrict__ C,
             int M, int Kc, int Nc)
{
    const int K  = 2*Kc;
    const int Nr = 2*Nc;
    __shared__ float As[2][16][128];
    __shared__ float Bs[2][16][64];

    int t  = threadIdx.x;          // 0..255
    int tx = t & 15;               // output col group 0..15 (4 cols each)
    int ty = t >> 4;               // output row group 0..15 (8 rows each)
    int row0 = blockIdx.y * 128;
    int col0 = blockIdx.x * 64;

    int ar = t >> 2;               // 0..63   (A staging row within half-tile)
    int ac = (t & 3) * 4;          // 0,4,8,12

    // B staging: thread -> one complex weight of the 8(kc) x 32(nc) slab
    int kcl = t >> 5;              // 0..7
    int ncl = t & 31;              // 0..31
    const int nc0 = col0 >> 1;     // complex col base

    float acc[8][4];
#pragma unroll
    for (int i = 0; i < 8; i++)
#pragma unroll
        for (int j = 0; j < 4; j++) acc[i][j] = 0.f;

    float4 av0, av1;
    float2 wv;
    auto load_tile = [&](int k0) {
        av0 = *(const float4*)&A[(size_t)(row0 + ar) * K + k0 + ac];
        av1 = *(const float4*)&A[(size_t)(row0 + 64 + ar) * K + k0 + ac];
        int kc = (k0 >> 1) + kcl;
        wv = *(const float2*)&W[((size_t)kc * Nc + nc0 + ncl) * 2];
    };
    auto store_tile = [&](int buf) {
        As[buf][ac+0][ar]      = av0.x;
        As[buf][ac+1][ar]      = av0.y;
        As[buf][ac+2][ar]      = av0.z;
        As[buf][ac+3][ar]      = av0.w;
        As[buf][ac+0][64 + ar] = av1.x;
        As[buf][ac+1][64 + ar] = av1.y;
        As[buf][ac+2][64 + ar] = av1.z;
        As[buf][ac+3][64 + ar] = av1.w;
        // expand complex weight to 2x2 real block
        *(float2*)&Bs[buf][2*kcl    ][2*ncl] = make_float2( wv.x, wv.y);
        *(float2*)&Bs[buf][2*kcl + 1][2*ncl] = make_float2(-wv.y, wv.x);
    };

    // prologue: stage slab 0
    load_tile(0);
    store_tile(0);
    __syncthreads();

    int buf = 0;
    for (int k0 = 0; k0 < K; k0 += 16) {
        bool has_next = (k0 + 16) < K;
        if (has_next) load_tile(k0 + 16);   // global loads overlap compute below

#pragma unroll
        for (int kk = 0; kk < 16; kk++) {
            float4 a0 = *(const float4*)&As[buf][kk][ty*8];
            float4 a1 = *(const float4*)&As[buf][kk][ty*8 + 4];
            float4 b  = *(const float4*)&Bs[buf][kk][tx*4];
            acc[0][0] += a0.x*b.x; acc[0][1] += a0.x*b.y; acc[0][2] += a0.x*b.z; acc[0][3] += a0.x*b.w;
            acc[1][0] += a0.y*b.x; acc[1][1] += a0.y*b.y; acc[1][2] += a0.y*b.z; acc[1][3] += a0.y*b.w;
            acc[2][0] += a0.z*b.x; acc[2][1] += a0.z*b.y; acc[2][2] += a0.z*b.z; acc[2][3] += a0.z*b.w;
            acc[3][0] += a0.w*b.x; acc[3][1] += a0.w*b.y; acc[3][2] += a0.w*b.z; acc[3][3] += a0.w*b.w;
            acc[4][0] += a1.x*b.x; acc[4][1] += a1.x*b.y; acc[4][2] += a1.x*b.z; acc[4][3] += a1.x*b.w;
            acc[5][0] += a1.y*b.x; acc[5][1] += a1.y*b.y; acc[5][2] += a1.y*b.z; acc[5][3] += a1.y*b.w;
            acc[6][0] += a1.z*b.x; acc[6][1] += a1.z*b.y; acc[6][2] += a1.z*b.z; acc[6][3] += a1.z*b.w;
            acc[7][0] += a1.w*b.x; acc[7][1] += a1.w*b.y; acc[7][2] += a1.w*b.z; acc[7][3] += a1.w*b.w;
        }

        if (has_next) {
            store_tile(buf ^ 1);
            __syncthreads();
            buf ^= 1;
        }
    }

    // epilogue: float4 per row
    float4 bv = make_float4(0.f, 0.f, 0.f, 0.f);
    if (bias) bv = *(const float4*)&bias[col0 + tx*4];
#pragma unroll
    for (int i = 0; i < 8; i++) {
        int r = row0 + ty*8 + i;
        float4 v = make_float4(acc[i][0] + bv.x, acc[i][1] + bv.y,
                               acc[i][2] + bv.z, acc[i][3] + bv.w);
        if (resid) {
            float4 rv = *(const float4*)&resid[(size_t)r * Nr + col0 + tx*4];
            v.x += rv.x; v.y += rv.y; v.z += rv.z; v.w += rv.w;
        }
        *(float4*)&C[(size_t)r * Nr + col0 + tx*4] = v;
    }
}

// ---------------------------------------------------------------------------
// RoPE + planar split.
// q:(B,N,INNER,2) -> qp[comp][b][h][n][dh] with rope
// kv:(B,N,2*INNER,2): k part (cols 0..INNER) rope -> kp; v part -> vp
// ---------------------------------------------------------------------------
__global__ void rope_split_kernel(const float* __restrict__ q,
                                  const float* __restrict__ kv,
                                  float* __restrict__ qp,
                                  float* __restrict__ kp,
                                  float* __restrict__ vp)
{
    int idx = blockIdx.x * blockDim.x + threadIdx.x;   // over B*N*INNER = 2^20
    if (idx >= BB*NN*INNER) return;
    int e = idx & (INNER-1);
    int n = (idx >> 9) & (NN-1);
    int b = idx >> 19;
    int h = e >> 6, dh = e & 63;

    // invfreq = 10000^(-dh/64)
    float invf = expf((float)dh * (-9.210340371976184f / 64.f));
    float ang = (float)n * invf;
    float sn, cs;
    sincosf(ang, &sn, &cs);

    size_t po = ((size_t)(b*HEADS + h) * NN + n) * DH + dh;

    // q
    {
        float r = q[(size_t)idx*2], im = q[(size_t)idx*2 + 1];
        qp[po]         = r*cs - im*sn;
        qp[po + PLANE] = r*sn + im*cs;
    }
    // k (first INNER cols of kv)
    {
        size_t kvi = ((size_t)(b*NN + n) * (2*INNER) + e) * 2;
        float r = kv[kvi], im = kv[kvi + 1];
        kp[po]         = r*cs - im*sn;
        kp[po + PLANE] = r*sn + im*cs;
    }
    // v (second INNER cols), no rope
    {
        size_t kvi = ((size_t)(b*NN + n) * (2*INNER) + INNER + e) * 2;
        vp[po]         = kv[kvi];
        vp[po + PLANE] = kv[kvi + 1];
    }
}

// ---------------------------------------------------------------------------
// Flash attention over one (variant, b, h): 4 variants
//   v0: attend(qr, kr, vr)   v1: attend(qr,-ki, vr)
//   v2: attend(qi, kr, vi)   v3: attend(qi,-ki, vi)
// blockIdx.y = v*16 + b*8 + h ; blockIdx.x = query row tile (64 rows)
// 64 threads, one query row per thread. ATT_SCALE folded into q registers;
// __expf (MUFU.EX2) for the online softmax.
// ---------------------------------------------------------------------------
__global__ void __launch_bounds__(64)
attn_kernel(const float* __restrict__ qp,
            const float* __restrict__ kp,
            const float* __restrict__ vp,
            float* __restrict__ outp)
{
    int vbh = blockIdx.y;
    int v   = vbh >> 4;
    int bh  = vbh & 15;
    int qc  = (v < 2) ? 0 : 1;
    int kc  = v & 1;
    float ksign = (v & 1) ? -1.f : 1.f;
    int vc  = qc;

    int tid = threadIdx.x;                 // 0..63
    int nq  = blockIdx.x * 64 + tid;

    __shared__ float Ks[64][64];
    __shared__ float Vs[64][64];

    const float* qrow = qp + (size_t)qc * PLANE + ((size_t)bh * NN + nq) * DH;
    float q[64];
#pragma unroll
    for (int d = 0; d < 64; d += 4) {
        float4 t4 = *(const float4*)&qrow[d];
        q[d]   = t4.x * ATT_SCALE;
        q[d+1] = t4.y * ATT_SCALE;
        q[d+2] = t4.z * ATT_SCALE;
        q[d+3] = t4.w * ATT_SCALE;
    }

    float o[64];
#pragma unroll
    for (int d = 0; d < 64; d++) o[d] = 0.f;
    float m = -1e30f, l = 0.f;

    const float* kbase = kp + (size_t)kc * PLANE + (size_t)bh * NN * DH;
    const float* vbase = vp + (size_t)vc * PLANE + (size_t)bh * NN * DH;

    for (int k0 = 0; k0 < NN; k0 += 64) {
        __syncthreads();
#pragma unroll 4
        for (int i = 0; i < 64; i++) {
            Ks[i][tid] = ksign * kbase[(size_t)(k0 + i) * DH + tid];
            Vs[i][tid] =         vbase[(size_t)(k0 + i) * DH + tid];
        }
        __syncthreads();

        for (int c = 0; c < 4; c++) {
            float s[16];
#pragma unroll
            for (int jj = 0; jj < 16; jj++) {
                const float* kr = Ks[c*16 + jj];
                float a = 0.f;
#pragma unroll
                for (int d = 0; d < 64; d++) a += q[d] * kr[d];
                s[jj] = a;
            }
            float mt = m;
#pragma unroll
            for (int jj = 0; jj < 16; jj++) mt = fmaxf(mt, s[jj]);
            float alpha = __expf(m - mt);
            m = mt;
            l *= alpha;
#pragma unroll
            for (int d = 0; d < 64; d++) o[d] *= alpha;
#pragma unroll
            for (int jj = 0; jj < 16; jj++) {
                float p = __expf(s[jj] - mt);
                l += p;
                const float* vr = Vs[c*16 + jj];
#pragma unroll
                for (int d = 0; d < 64; d++) o[d] += p * vr[d];
            }
        }
    }

    float inv = 1.f / l;
    float* orow = outp + (size_t)v * PLANE + ((size_t)bh * NN + nq) * DH;
#pragma unroll
    for (int d = 0; d < 64; d++) orow[d] = o[d] * inv;
}

// ---------------------------------------------------------------------------
// Combine 4 attention planes to complex (B,N,INNER,2):
//   re = rr - ii, im = ri + ir
// ---------------------------------------------------------------------------
__global__ void combine_kernel(const float* __restrict__ attn, float* __restrict__ o)
{
    int idx = blockIdx.x * blockDim.x + threadIdx.x;   // over B*N*INNER
    if (idx >= BB*NN*INNER) return;
    int e = idx & (INNER-1);
    int n = (idx >> 9) & (NN-1);
    int b = idx >> 19;
    int h = e >> 6, dh = e & 63;
    size_t a = ((size_t)(b*HEADS + h) * NN + n) * DH + dh;
    float rr = attn[a];
    float ri = attn[a + (size_t)1*PLANE];
    float ir = attn[a + (size_t)2*PLANE];
    float ii = attn[a + (size_t)3*PLANE];
    o[(size_t)idx*2]     = rr - ii;
    o[(size_t)idx*2 + 1] = ri + ir;
}

// ---------------------------------------------------------------------------
// FF nonlinearity: h <- relu(|h| + mod_bias)^2 * exp(i*angle(h))
// ---------------------------------------------------------------------------
__global__ void ffact_kernel(float* __restrict__ h, const float* __restrict__ mod_bias, int l)
{
    int idx = blockIdx.x * blockDim.x + threadIdx.x;   // over B*N*FF
    if (idx >= BB*NN*FF) return;
    float mb = mod_bias[l];
    float hr = h[(size_t)idx*2], hi = h[(size_t)idx*2 + 1];
    float mag = sqrtf(hr*hr + hi*hi);
    float t = mag + mb;
    float c = (t > 0.f) ? t*t : 0.f;
    float orr, oi;
    if (mag > 0.f) {
        float s = c / mag;
        orr = hr * s; oi = hi * s;
    } else {
        orr = c; oi = 0.f;
    }
    h[(size_t)idx*2]     = orr;
    h[(size_t)idx*2 + 1] = oi;
}

// ---------------------------------------------------------------------------
// Launch
// ---------------------------------------------------------------------------
extern "C" void kernel_launch(void* const* d_in, const int* in_sizes, int n_in,
                              void* d_out, int out_size)
{
    const float* x          = (const float*)d_in[0];
    const float* gamma_attn = (const float*)d_in[1];
    const float* Wq         = (const float*)d_in[2];
    const float* Wkv        = (const float*)d_in[3];
    const float* Wo         = (const float*)d_in[4];
    const float* gamma_ff   = (const float*)d_in[5];
    const float* W1         = (const float*)d_in[6];
    const float* b1         = (const float*)d_in[7];
    const float* mod_bias   = (const float*)d_in[8];
    const float* W2         = (const float*)d_in[9];
    const float* b2         = (const float*)d_in[10];
    const float* gamma_fin  = (const float*)d_in[11];

    float *gx, *gh, *gq, *gkv, *gqp, *gkp, *gvp, *gattn, *go, *gff;
    cudaGetSymbolAddress((void**)&gx,   g_x);
    cudaGetSymbolAddress((void**)&gh,   g_h);
    cudaGetSymbolAddress((void**)&gq,   g_q);
    cudaGetSymbolAddress((void**)&gkv,  g_kv);
    cudaGetSymbolAddress((void**)&gqp,  g_qp);
    cudaGetSymbolAddress((void**)&gkp,  g_kp);
    cudaGetSymbolAddress((void**)&gvp,  g_vp);
    cudaGetSymbolAddress((void**)&gattn,g_attn);
    cudaGetSymbolAddress((void**)&go,   g_o);
    cudaGetSymbolAddress((void**)&gff,  g_ff);

    // x -> g_x
    {
        int n4 = ROWS*DIMM*2/4;
        copy_kernel<<<(n4 + 255)/256, 256>>>((const float4*)x, (float4*)gx, n4);
    }

    const int ew_blocks  = (BB*NN*INNER + 255)/256;   // 4096
    const int ff_blocks  = (BB*NN*FF + 255)/256;      // 16384

    for (int l = 0; l < 2; l++) {
        // attention block
        rmsnorm_kernel<<<ROWS, 256>>>(gx, gamma_attn + l*DIMM*2, gh);
        cgemm_kernel<<<dim3(16, 16), 256>>>(gh, Wq  + (size_t)l*DIMM*INNER*2,
                                            nullptr, nullptr, gq, ROWS, DIMM, INNER);
        cgemm_kernel<<<dim3(32, 16), 256>>>(gh, Wkv + (size_t)l*DIMM*2*INNER*2,
                                            nullptr, nullptr, gkv, ROWS, DIMM, 2*INNER);
        rope_split_kernel<<<ew_blocks, 256>>>(gq, gkv, gqp, gkp, gvp);
        attn_kernel<<<dim3(16, 64), 64>>>(gqp, gkp, gvp, gattn);
        combine_kernel<<<ew_blocks, 256>>>(gattn, go);
        cgemm_kernel<<<dim3(16, 16), 256>>>(go, Wo + (size_t)l*INNER*DIMM*2,
                                            nullptr, gx, gx, ROWS, INNER, DIMM);
        // feed-forward block
        rmsnorm_kernel<<<ROWS, 256>>>(gx, gamma_ff + l*DIMM*2, gh);
        cgemm_kernel<<<dim3(64, 16), 256>>>(gh, W1 + (size_t)l*DIMM*FF*2,
                                            b1 + (size_t)l*FF*2, nullptr, gff, ROWS, DIMM, FF);
        ffact_kernel<<<ff_blocks, 256>>>(gff, mod_bias, l);
        cgemm_kernel<<<dim3(16, 16), 256>>>(gff, W2 + (size_t)l*FF*DIMM*2,
                                            b2 + (size_t)l*DIMM*2, gx, gx, ROWS, FF, DIMM);
    }

    rmsnorm_kernel<<<ROWS, 256>>>(gx, gamma_fin, (float*)d_out);
}